// round 3
// baseline (speedup 1.0000x reference)
#include <cuda_runtime.h>
#include <math.h>

namespace {

using u64 = unsigned long long;

constexpr int B      = 4096;
constexpr int NHID   = 512;
constexpr int BR     = 32;
constexpr int NG2    = 1024;
constexpr int WSLICE = NHID * BR;
constexpr int MAXIT  = 3584;

// ---- persistent scratch ----
__device__ int   g_perm[B];
__device__ int2  g_items[MAXIT];     // {start | count<<16, node}
__device__ int   g_nitems;
__device__ int   g_done[B];
__device__ float g_q0[B];
__device__ float g_q1[B];
__device__ float g_q2[B];

// ---- f32x2 helpers (PTX-only packed FMA) ----
__device__ __forceinline__ u64 fma2(u64 a, u64 b, u64 c) {
    u64 d; asm("fma.rn.f32x2 %0, %1, %2, %3;" : "=l"(d) : "l"(a), "l"(b), "l"(c));
    return d;
}
__device__ __forceinline__ u64 add2(u64 a, u64 b) {
    u64 d; asm("add.rn.f32x2 %0, %1, %2;" : "=l"(d) : "l"(a), "l"(b));
    return d;
}
__device__ __forceinline__ u64 dup2(float x) {
    u64 d; asm("mov.b64 %0, {%1, %1};" : "=l"(d) : "r"(__float_as_uint(x)));
    return d;
}
__device__ __forceinline__ float lo32(u64 a) { return __uint_as_float((unsigned)a); }
__device__ __forceinline__ float hi32(u64 a) { return __uint_as_float((unsigned)(a >> 32)); }

__device__ __forceinline__ int warp_incl_scan(int v) {
    int lane = threadIdx.x & 31;
    #pragma unroll
    for (int o = 1; o < 32; o <<= 1) {
        int n = __shfl_up_sync(0xffffffffu, v, o);
        if (lane >= o) v += n;
    }
    return v;
}

// ================= setup: one block, 1024 threads =================
__global__ __launch_bounds__(1024)
void hs_sort(const int* __restrict__ labels)
{
    __shared__ int scnt[NG2];
    __shared__ int soff[NG2 + 1];
    __shared__ int srun[NG2];
    __shared__ int sA[33];
    __shared__ int sB[33];
    __shared__ int s_H, s_L, s_it1base;

    const int tid  = threadIdx.x;
    const int lane = tid & 31;
    const int w    = tid >> 5;

    ((int4*)g_done)[tid] = make_int4(0, 0, 0, 0);
    scnt[tid] = 0;
    srun[tid] = 0;
    __syncthreads();

    const int4 lab4 = ((const int4*)labels)[tid];
    atomicAdd(&scnt[lab4.x >> 5], 1);
    atomicAdd(&scnt[lab4.y >> 5], 1);
    atomicAdd(&scnt[lab4.z >> 5], 1);
    atomicAdd(&scnt[lab4.w >> 5], 1);
    __syncthreads();

    const int c = scnt[tid];

    // scan 1: exclusive offsets of groups
    {
        int inc = warp_incl_scan(c);
        if (lane == 31) sA[w] = inc;
        __syncthreads();
        if (w == 0) { int t = sA[lane]; int ti = warp_incl_scan(t); sA[lane] = ti - t; }
        __syncthreads();
        int off = inc - c + sA[w];
        soff[tid] = off;
        if (tid == NG2 - 1) soff[NG2] = off + c;
    }
    __syncthreads();
    const int off = soff[tid];

    // scan 2: level-2 item offsets (batch of 4 per group)
    const int nit2 = (c + 3) >> 2;
    int ioff2, tot2;
    {
        int inc2 = warp_incl_scan(nit2);
        if (lane == 31) sB[w] = inc2;
        __syncthreads();
        if (w == 0) {
            int t = sB[lane]; int ti = warp_incl_scan(t);
            sB[lane] = ti - t;
            if (lane == 31) sB[32] = ti;
        }
        __syncthreads();
        ioff2 = inc2 - nit2 + sB[w];
        tot2  = sB[32];
    }

    // scatter into g_perm
    {
        int i = tid * 4;
        int g0 = lab4.x >> 5, g1 = lab4.y >> 5, g2 = lab4.z >> 5, g3 = lab4.w >> 5;
        g_perm[soff[g0] + atomicAdd(&srun[g0], 1)] = i;
        g_perm[soff[g1] + atomicAdd(&srun[g1], 1)] = i + 1;
        g_perm[soff[g2] + atomicAdd(&srun[g2], 1)] = i + 2;
        g_perm[soff[g3] + atomicAdd(&srun[g3], 1)] = i + 3;
    }

    // level-1 items (32 groups of 32 leaf-groups each), batch 8
    int c1 = 0, nit1 = 0, it1off = 0, st1 = 0;
    if (tid < 32) {
        st1 = soff[tid * 32];
        c1  = soff[(tid + 1) * 32] - st1;
        nit1 = (c1 + 7) >> 3;
        int i1 = warp_incl_scan(nit1);
        it1off = i1 - nit1;
        int tot1 = __shfl_sync(0xffffffffu, i1, 31);
        if (tid == 0) {
            s_it1base = 512;
            s_H = 512 + tot1;    // heavy items: L0 + L1 (batch 8)
        }
    }
    __syncthreads();
    if (tid == 0) s_L = tot2;
    __syncthreads();
    const int H = s_H, L = s_L;
    const int m = min(H, L);

    // interleave heavy/light item placement for SMSP balance
    auto heavy_pos = [&](int k) { return (k < m) ? 2 * k     : m + k; };
    auto light_pos = [&](int k) { return (k < m) ? 2 * k + 1 : m + k; };

    // level-0 items: 512 items of 8 sorted positions, node 0
    if (tid < 512)
        g_items[heavy_pos(tid)] = make_int2((tid * 8) | (8 << 16), 0);

    if (tid < 32) {
        for (int k = 0; k < nit1; k++) {
            int cc = min(8, c1 - 8 * k);
            g_items[heavy_pos(512 + it1off + k)] =
                make_int2((st1 + 8 * k) | (cc << 16), 1 + tid);
        }
    }

    for (int k = 0; k < nit2; k++) {
        int cc = min(4, c - 4 * k);
        g_items[light_pos(ioff2 + k)] = make_int2((off + 4 * k) | (cc << 16), 33 + tid);
    }

    if (tid == 0) g_nitems = H + L;
}

// ================= main compute =================

template <int BATCH>
__device__ __forceinline__ void process_item(
    const float* __restrict__ inputs,
    const int*   __restrict__ labels,
    const float* __restrict__ W,
    float*       __restrict__ out,
    int start, int count, int node, int lane)
{
    const int cg = lane & 7;      // 4-column group
    const int hs = lane >> 3;     // h-stripe within 16-chunk

    int shift;
    float* qdst;
    if (node == 0)      { shift = 10; qdst = g_q0; }
    else if (node < 33) { shift = 5;  qdst = g_q1; }
    else                { shift = 0;  qdst = g_q2; }

    int idx[BATCH], step[BATCH];
    const float* xp[BATCH];
    #pragma unroll
    for (int s = 0; s < BATCH; s++) {
        int pos = start + ((s < count) ? s : (count - 1));
        int i = g_perm[pos];
        idx[s]  = i;
        step[s] = (labels[i] >> shift) & 31;
        xp[s]   = inputs + (size_t)i * NHID;
    }

    const float* __restrict__ Wn = W + (size_t)node * WSLICE + cg * 4;

    u64 acc0[BATCH], acc1[BATCH];      // (c0,c1) and (c2,c3) packed
    #pragma unroll
    for (int s = 0; s < BATCH; s++) { acc0[s] = 0ull; acc1[s] = 0ull; }

    for (int hb = 0; hb < NHID; hb += 16) {
        const int h0 = hb + hs * 4;
        ulonglong2 wv[4];
        #pragma unroll
        for (int j = 0; j < 4; j++)
            wv[j] = *(const ulonglong2*)&Wn[(h0 + j) * BR];
        #pragma unroll
        for (int s = 0; s < BATCH; s++) {
            const float4 xv = *(const float4*)&xp[s][h0];
            #pragma unroll
            for (int j = 0; j < 4; j++) {
                const u64 xd = dup2((&xv.x)[j]);
                acc0[s] = fma2(wv[j].x, xd, acc0[s]);
                acc1[s] = fma2(wv[j].y, xd, acc1[s]);
            }
        }
    }

    // reduce over the 4 h-stripes (lanes cg, cg+8, cg+16, cg+24)
    #pragma unroll
    for (int o = 8; o <= 16; o <<= 1)
        #pragma unroll
        for (int s = 0; s < BATCH; s++) {
            acc0[s] = add2(acc0[s], __shfl_xor_sync(0xffffffffu, acc0[s], o));
            acc1[s] = add2(acc1[s], __shfl_xor_sync(0xffffffffu, acc1[s], o));
        }

    // per-sample softmax across the 8 column-group lanes
    float q[BATCH];
    #pragma unroll
    for (int s = 0; s < BATCH; s++) {
        const float a0 = lo32(acc0[s]), a1 = hi32(acc0[s]);
        const float a2 = lo32(acc1[s]), a3 = hi32(acc1[s]);
        float mx = fmaxf(fmaxf(a0, a1), fmaxf(a2, a3));
        #pragma unroll
        for (int o = 1; o < 8; o <<= 1)
            mx = fmaxf(mx, __shfl_xor_sync(0xffffffffu, mx, o));
        float e = __expf(a0 - mx) + __expf(a1 - mx) + __expf(a2 - mx) + __expf(a3 - mx);
        #pragma unroll
        for (int o = 1; o < 8; o <<= 1)
            e += __shfl_xor_sync(0xffffffffu, e, o);
        const float lse = mx + __logf(e);
        const int r = step[s] & 3;
        float v = (r == 0) ? a0 : (r == 1) ? a1 : (r == 2) ? a2 : a3;
        float sel = (cg == (step[s] >> 2)) ? v : -INFINITY;
        #pragma unroll
        for (int o = 1; o < 8; o <<= 1)
            sel = fmaxf(sel, __shfl_xor_sync(0xffffffffu, sel, o));
        q[s] = sel - lse;
    }

    // release q, bump done counter; third arriver combines and writes out
    #pragma unroll
    for (int s = 0; s < BATCH; s++)
        if (s < count && lane == s) __stcg(&qdst[idx[s]], q[s]);
    __threadfence();
    #pragma unroll
    for (int s = 0; s < BATCH; s++) {
        if (s < count && lane == s) {
            int old = atomicAdd(&g_done[idx[s]], 1);
            if (old == 2) {
                __threadfence();
                float t = __ldcg(&g_q0[idx[s]]) + __ldcg(&g_q1[idx[s]])
                        + __ldcg(&g_q2[idx[s]]);
                out[idx[s]] = __expf(t);
            }
        }
    }
}

__global__ __launch_bounds__(256)
void hs_main(const float* __restrict__ inputs,
             const int*   __restrict__ labels,
             const float* __restrict__ W,
             float*       __restrict__ out)
{
    const int lane = threadIdx.x & 31;
    const int gw   = (blockIdx.x << 3) + (threadIdx.x >> 5);
    const int nw   = gridDim.x << 3;
    const int nit  = g_nitems;

    for (int it = gw; it < nit; it += nw) {
        const int2 item  = g_items[it];
        const int  start = item.x & 0xffff;
        const int  count = item.x >> 16;
        const int  node  = item.y;
        switch (count) {
            case 1:  process_item<1>(inputs, labels, W, out, start, 1, node, lane); break;
            case 2:  process_item<2>(inputs, labels, W, out, start, 2, node, lane); break;
            case 3:  process_item<3>(inputs, labels, W, out, start, 3, node, lane); break;
            case 4:  process_item<4>(inputs, labels, W, out, start, 4, node, lane); break;
            default: process_item<8>(inputs, labels, W, out, start, count, node, lane); break;
        }
    }
}

} // namespace

extern "C" void kernel_launch(void* const* d_in, const int* in_sizes, int n_in,
                              void* d_out, int out_size)
{
    const float* inputs = (const float*)d_in[0];
    const int*   labels = (const int*)d_in[1];
    const float* W      = (const float*)d_in[2];
    float*       out    = (float*)d_out;

    hs_sort<<<1, 1024>>>(labels);
    hs_main<<<296, 256>>>(inputs, labels, W, out);
}

// round 5
// speedup vs baseline: 1.6547x; 1.6547x over previous
#include <cuda_runtime.h>
#include <math.h>

namespace {

using u64 = unsigned long long;

constexpr int B      = 4096;
constexpr int NHID   = 512;
constexpr int BR     = 32;
constexpr int NG2    = 1024;
constexpr int WSLICE = NHID * BR;
constexpr int MAXIT  = 4096;

// ---- persistent scratch ----
__device__ int   g_perm[B];
__device__ int2  g_items[MAXIT];     // {start | count<<16, node}
__device__ int   g_nitems;
__device__ float g_q0[B];
__device__ float g_q1[B];
__device__ float g_q2[B];

// ---- f32x2 helpers (PTX-only packed FMA) ----
__device__ __forceinline__ u64 fma2(u64 a, u64 b, u64 c) {
    u64 d; asm("fma.rn.f32x2 %0, %1, %2, %3;" : "=l"(d) : "l"(a), "l"(b), "l"(c));
    return d;
}
__device__ __forceinline__ u64 add2(u64 a, u64 b) {
    u64 d; asm("add.rn.f32x2 %0, %1, %2;" : "=l"(d) : "l"(a), "l"(b));
    return d;
}
__device__ __forceinline__ u64 dup2(float x) {
    u64 d; asm("mov.b64 %0, {%1, %1};" : "=l"(d) : "r"(__float_as_uint(x)));
    return d;
}
__device__ __forceinline__ float lo32(u64 a) { return __uint_as_float((unsigned)a); }
__device__ __forceinline__ float hi32(u64 a) { return __uint_as_float((unsigned)(a >> 32)); }

__device__ __forceinline__ int warp_incl_scan(int v) {
    int lane = threadIdx.x & 31;
    #pragma unroll
    for (int o = 1; o < 32; o <<= 1) {
        int n = __shfl_up_sync(0xffffffffu, v, o);
        if (lane >= o) v += n;
    }
    return v;
}

// ================= setup: one block, 1024 threads =================
__global__ __launch_bounds__(1024)
void hs_sort(const int* __restrict__ labels)
{
    __shared__ int scnt[NG2];
    __shared__ int soff[NG2 + 1];
    __shared__ int srun[NG2];
    __shared__ int sA[33];
    __shared__ int sB[33];
    __shared__ int s_base2;

    const int tid  = threadIdx.x;
    const int lane = tid & 31;
    const int w    = tid >> 5;

    scnt[tid] = 0;
    srun[tid] = 0;
    __syncthreads();

    const int4 lab4 = ((const int4*)labels)[tid];
    atomicAdd(&scnt[lab4.x >> 5], 1);
    atomicAdd(&scnt[lab4.y >> 5], 1);
    atomicAdd(&scnt[lab4.z >> 5], 1);
    atomicAdd(&scnt[lab4.w >> 5], 1);
    __syncthreads();

    const int c = scnt[tid];

    // scan 1: exclusive offsets of leaf groups
    {
        int inc = warp_incl_scan(c);
        if (lane == 31) sA[w] = inc;
        __syncthreads();
        if (w == 0) { int t = sA[lane]; int ti = warp_incl_scan(t); sA[lane] = ti - t; }
        __syncthreads();
        int off = inc - c + sA[w];
        soff[tid] = off;
        if (tid == NG2 - 1) soff[NG2] = off + c;
    }
    __syncthreads();
    const int off = soff[tid];

    // scan 2: level-2 item offsets (batch of 8 per group)
    const int nit2 = (c + 7) >> 3;
    int ioff2, tot2;
    {
        int inc2 = warp_incl_scan(nit2);
        if (lane == 31) sB[w] = inc2;
        __syncthreads();
        if (w == 0) {
            int t = sB[lane]; int ti = warp_incl_scan(t);
            sB[lane] = ti - t;
            if (lane == 31) sB[32] = ti;
        }
        __syncthreads();
        ioff2 = inc2 - nit2 + sB[w];
        tot2  = sB[32];
    }

    // scatter into g_perm
    {
        int i = tid * 4;
        int g0 = lab4.x >> 5, g1 = lab4.y >> 5, g2 = lab4.z >> 5, g3 = lab4.w >> 5;
        g_perm[soff[g0] + atomicAdd(&srun[g0], 1)] = i;
        g_perm[soff[g1] + atomicAdd(&srun[g1], 1)] = i + 1;
        g_perm[soff[g2] + atomicAdd(&srun[g2], 1)] = i + 2;
        g_perm[soff[g3] + atomicAdd(&srun[g3], 1)] = i + 3;
    }

    // level-0 items: 512 items of 8 sorted positions, node 0
    if (tid < 512)
        g_items[tid] = make_int2((tid * 8) | (8 << 16), 0);

    // level-1 items (32 groups of 32 leaf groups), batch 8
    if (tid < 32) {
        int st1 = soff[tid * 32];
        int c1  = soff[(tid + 1) * 32] - st1;
        int nit1 = (c1 + 7) >> 3;
        int i1 = warp_incl_scan(nit1);
        int it1off = i1 - nit1;
        int tot1 = __shfl_sync(0xffffffffu, i1, 31);
        if (tid == 0) s_base2 = 512 + tot1;
        for (int k = 0; k < nit1; k++) {
            int cc = min(8, c1 - 8 * k);
            g_items[512 + it1off + k] = make_int2((st1 + 8 * k) | (cc << 16), 1 + tid);
        }
    }
    __syncthreads();
    const int base2 = s_base2;

    // level-2 items, batch 8
    for (int k = 0; k < nit2; k++) {
        int cc = min(8, c - 8 * k);
        g_items[base2 + ioff2 + k] = make_int2((off + 8 * k) | (cc << 16), 33 + tid);
    }

    if (tid == 0) g_nitems = base2 + tot2;
}

// ================= main compute: one warp per item, BATCH=8 =================
__global__ __launch_bounds__(256)
void hs_main(const float* __restrict__ inputs,
             const int*   __restrict__ labels,
             const float* __restrict__ W)
{
    const int lane = threadIdx.x & 31;
    const int cg   = lane & 7;      // 4-column group
    const int hs   = lane >> 3;     // h-stripe within 16-chunk
    const int gw   = (blockIdx.x << 3) + (threadIdx.x >> 5);
    const int nw   = gridDim.x << 3;
    const int nit  = g_nitems;

    for (int it = gw; it < nit; it += nw) {
        const int2 item  = g_items[it];
        const int  start = item.x & 0xffff;
        const int  count = item.x >> 16;
        const int  node  = item.y;

        int shift;
        float* qdst;
        if (node == 0)      { shift = 10; qdst = g_q0; }
        else if (node < 33) { shift = 5;  qdst = g_q1; }
        else                { shift = 0;  qdst = g_q2; }

        int idx[8];
        u64 steps = 0;    // 5 bits per sample
        const float* xp[8];
        #pragma unroll
        for (int s = 0; s < 8; s++) {
            int pos = start + ((s < count) ? s : (count - 1));
            int i = g_perm[pos];
            idx[s] = i;
            steps |= (u64)((labels[i] >> shift) & 31) << (5 * s);
            xp[s]  = inputs + (size_t)i * NHID;
        }

        const float* __restrict__ Wn = W + (size_t)node * WSLICE + cg * 4;

        u64 acc0[8], acc1[8];       // (c0,c1),(c2,c3) packed per sample
        #pragma unroll
        for (int s = 0; s < 8; s++) { acc0[s] = 0ull; acc1[s] = 0ull; }

        for (int hb = 0; hb < NHID; hb += 16) {
            const int h0 = hb + hs * 4;
            ulonglong2 wv[4];
            #pragma unroll
            for (int j = 0; j < 4; j++)
                wv[j] = *(const ulonglong2*)&Wn[(h0 + j) * BR];
            float4 xv[8];
            #pragma unroll
            for (int s = 0; s < 8; s++)
                xv[s] = *(const float4*)&xp[s][h0];
            #pragma unroll
            for (int j = 0; j < 4; j++) {
                #pragma unroll
                for (int s = 0; s < 8; s++) {
                    const u64 xd = dup2((&xv[s].x)[j]);
                    acc0[s] = fma2(wv[j].x, xd, acc0[s]);
                    acc1[s] = fma2(wv[j].y, xd, acc1[s]);
                }
            }
        }

        // reduce over the 4 h-stripes (lanes cg, cg+8, cg+16, cg+24)
        #pragma unroll
        for (int o = 8; o <= 16; o <<= 1)
            #pragma unroll
            for (int s = 0; s < 8; s++) {
                acc0[s] = add2(acc0[s], __shfl_xor_sync(0xffffffffu, acc0[s], o));
                acc1[s] = add2(acc1[s], __shfl_xor_sync(0xffffffffu, acc1[s], o));
            }

        // per-sample softmax across the 8 column-group lanes
        #pragma unroll
        for (int s = 0; s < 8; s++) {
            const int st = (int)(steps >> (5 * s)) & 31;
            const float a0 = lo32(acc0[s]), a1 = hi32(acc0[s]);
            const float a2 = lo32(acc1[s]), a3 = hi32(acc1[s]);
            float mx = fmaxf(fmaxf(a0, a1), fmaxf(a2, a3));
            #pragma unroll
            for (int o = 1; o < 8; o <<= 1)
                mx = fmaxf(mx, __shfl_xor_sync(0xffffffffu, mx, o));
            float e = __expf(a0 - mx) + __expf(a1 - mx) + __expf(a2 - mx) + __expf(a3 - mx);
            #pragma unroll
            for (int o = 1; o < 8; o <<= 1)
                e += __shfl_xor_sync(0xffffffffu, e, o);
            const float lse = mx + __logf(e);
            const int r = st & 3;
            float v = (r == 0) ? a0 : (r == 1) ? a1 : (r == 2) ? a2 : a3;
            float sel = (cg == (st >> 2)) ? v : -INFINITY;
            #pragma unroll
            for (int o = 1; o < 8; o <<= 1)
                sel = fmaxf(sel, __shfl_xor_sync(0xffffffffu, sel, o));
            if (s < count && lane == s) qdst[idx[s]] = sel - lse;
        }
    }
}

__global__ void hs_combine(float* __restrict__ out)
{
    int i = blockIdx.x * blockDim.x + threadIdx.x;   // 16 x 256
    out[i] = __expf(g_q0[i] + g_q1[i] + g_q2[i]);
}

} // namespace

extern "C" void kernel_launch(void* const* d_in, const int* in_sizes, int n_in,
                              void* d_out, int out_size)
{
    const float* inputs = (const float*)d_in[0];
    const int*   labels = (const int*)d_in[1];
    const float* W      = (const float*)d_in[2];
    float*       out    = (float*)d_out;

    hs_sort   <<<1, 1024>>>(labels);
    hs_main   <<<296, 256>>>(inputs, labels, W);
    hs_combine<<<16, 256>>>(out);
}